// round 15
// baseline (speedup 1.0000x reference)
#include <cuda_runtime.h>
#include <stdint.h>

// Problem: B x N fp32 scores. Outputs (concatenated into float d_out):
//   [0, B*N)      portfolio_weights (sparse +softmax(top20), -softmax(bot20))
//   [B*N, 2*B*N)  sorted_indices of argsort(-scores) as float
#define N_COLS 8192
#define NB     1536   // bucket id space (used ids <= 1500)
#define NT     1024   // threads per CTA (one CTA per row)
#define NWARP  32
#define KBUCK  1500   // equal-probability bucket budget (avg ~5.5/bucket)

// 13-bit-prefix bucket table. For prefix p = dk >> 19:
//   entry = (base << 5) | cells   (base <= 1500 fits 11 bits, cells <= 31)
//   bucket = base + ((dk & 0x7FFFF) * cells) >> 19
__device__ unsigned short g_tab13[8192];

__device__ __forceinline__ float key_to_val(unsigned int dk) {
    unsigned int ukey = ~dk;
    return (ukey & 0x80000000u) ? __uint_as_float(ukey ^ 0x80000000u)
                                : __uint_as_float(~ukey);
}

__device__ __forceinline__ unsigned int desc_key(float x) {
    unsigned int u = __float_as_uint(x);
    unsigned int ukey = (u & 0x80000000u) ? ~u : (u | 0x80000000u);
    return ~ukey;   // ascending key == descending value
}

// Build table in ONE kernel (1 block x 1024 threads).
__global__ void pg_build13() {
    __shared__ unsigned int tmax[NT];
    __shared__ unsigned int fixed[8193];
    int t = threadIdx.x;
    unsigned int v[8];
    unsigned int cm = 0;
#pragma unroll
    for (int i = 0; i < 8; i++) {
        int p = t * 8 + i;
        float x = key_to_val(((unsigned int)p) << 19);
        float F;
        if (!(x == x)) F = (p < 4096) ? 0.f : 1.f;            // NaN prefixes
        else           F = normcdff(-fminf(fmaxf(x, -30.f), 30.f)); // 1-Phi(x)
        int b = (int)floorf(F * (float)KBUCK);
        b = b < 0 ? 0 : (b > KBUCK ? KBUCK : b);
        v[i] = (unsigned int)b;
        cm = max(cm, v[i]);
    }
    tmax[t] = cm;
    __syncthreads();
    for (int d = 1; d < NT; d <<= 1) {
        unsigned int w = (t >= d) ? tmax[t - d] : 0u;
        __syncthreads();
        if (t >= d) tmax[t] = max(tmax[t], w);
        __syncthreads();
    }
    unsigned int run = (t == 0) ? 0u : tmax[t - 1];
#pragma unroll
    for (int i = 0; i < 8; i++) {
        run = max(run, v[i]);
        fixed[t * 8 + i] = run;
    }
    if (t == 0) fixed[8192] = KBUCK;
    __syncthreads();
    for (int p = t; p < 8192; p += NT) {
        unsigned int b0 = fixed[p];
        unsigned int c = fixed[p + 1] - b0;
        if (c > 31u) c = 31u;
        g_tab13[p] = (unsigned short)((b0 << 5) | c);
    }
}

// ---------------------------------------------------------------------------
// Element ownership: warp wid owns elements [wid*256, wid*256+256);
// lane handles idx = wid*256 + k*32 + lane (k-major) so scatter position
// order within a bucket equals ascending original index (exact stable ties).
//
// SMEM layout (bytes):
//   [0,     32768)  keys u32[8192]   scattered keys, bucket-grouped (ph3+)
//   [32768, 49152)  sidx u16[8192]   rank->index (ph4+)
//                   ALIAS: tab13 u16[8192] bucket table (ph0-1 only)
//   [49152, 98304)  whist u8[32][1536] per-warp counts -> excl offs (ph1-3)
//   [98304,104452)  base u32[1537]   global excl bucket offsets + sentinel
//   [104464,104592) wsum u32[32]     scan staging
//   [104592,104752) sc_val f32[40]
//   [104752,104912) sc_idx i32[40]
// Total 104912 B -> two CTAs per SM (209824 <= 228KB) with regs <= 32.
// ---------------------------------------------------------------------------
#define SMEM_BYTES 104912

__global__ void __launch_bounds__(NT, 2)
pg_sort_kernel(const float* __restrict__ in, float* __restrict__ out,
               int B, int write_indices) {
    extern __shared__ unsigned char smem_raw[];
    unsigned int*   keys  = (unsigned int*)smem_raw;
    unsigned short* sidx  = (unsigned short*)(smem_raw + 32768);
    unsigned short* tab13 = (unsigned short*)(smem_raw + 32768);  // alias ph0-1
    unsigned char*  whist = (unsigned char*)(smem_raw + 49152);
    unsigned int*   base  = (unsigned int*)(smem_raw + 98304);
    unsigned int*   wsum  = (unsigned int*)(smem_raw + 104464);
    float* sc_val = (float*)(smem_raw + 104592);
    int*   sc_idx = (int*)  (smem_raw + 104752);

    int row = blockIdx.x;
    int tid = threadIdx.x;
    int lane = tid & 31;
    int wid = tid >> 5;
    const float* rowp = in + (size_t)row * N_COLS;
    float* ow = out + (size_t)row * N_COLS;

    // Early: zero the output weights row NOW so the 32KB of STG drains
    // behind phases 1-4 (the 40-weight scatter is ordered after via the
    // intervening __syncthreads, which fence global within the block).
    {
        float4* ow4 = (float4*)ow;
        float4 z = make_float4(0.f, 0.f, 0.f, 0.f);
        ow4[tid] = z;
        ow4[tid + NT] = z;
    }

    // Phase 0: zero per-warp histograms (48KB) + copy table to smem (16KB)
    {
        uint4* wz = (uint4*)whist;
        uint4 z4 = make_uint4(0, 0, 0, 0);
        wz[tid] = z4;
        wz[tid + NT] = z4;
        wz[tid + 2 * NT] = z4;
        unsigned int* tsrc = (unsigned int*)g_tab13;
        unsigned int* tdst = (unsigned int*)tab13;
#pragma unroll
        for (int j = 0; j < 4; j++) tdst[tid + j * NT] = tsrc[tid + j * NT];
    }
    __syncthreads();

    // ---- Phase 1: keys + batched table lookups, then branchless match RMW
    unsigned int dk[8];
    unsigned int bk[8];                      // packed (bucket<<8)|warp_rank
    {
        int ebase = wid * 256 + lane;
        float vv[8];
#pragma unroll
        for (int k = 0; k < 8; k++) vv[k] = rowp[ebase + k * 32];  // MLP=8
        unsigned int ee[8];
#pragma unroll
        for (int k = 0; k < 8; k++) dk[k] = desc_key(vv[k]);       // pure ALU
#pragma unroll
        for (int k = 0; k < 8; k++) ee[k] = (unsigned int)tab13[dk[k] >> 19]; // MLP=8
        unsigned char* wh = whist + wid * NB;
        unsigned int ltmask = (1u << lane) - 1u;
#pragma unroll
        for (int k = 0; k < 8; k++) {
            unsigned int b = (ee[k] >> 5) + (((dk[k] & 0x7FFFFu) * (ee[k] & 31u)) >> 19);
            unsigned int mask = __match_any_sync(0xFFFFFFFFu, b);
            unsigned int before = (unsigned int)wh[b];                 // all lanes
            wh[b] = (unsigned char)(before + (unsigned int)__popc(mask)); // same val
            bk[k] = (b << 8) | (before + (unsigned int)__popc(mask & ltmask));
            __syncwarp();
        }
    }
    __syncthreads();

    // ---- Phase 2: SIMD cross-warp exclusive offsets.
    // Thread t < 384 owns buckets [4t, 4t+4): u32 loads process 4 u8
    // counters at once; __vadd4 = per-byte add (no cross-byte carry).
    {
        unsigned int run = 0, tsum = 0, inc = 0;
        if (tid < 384) {
#pragma unroll
            for (int w = 0; w < NWARP; w++) {
                unsigned int* p32 = (unsigned int*)(whist + w * NB + 4 * tid);
                unsigned int c = *p32;
                *p32 = run;                    // packed per-warp exclusive
                run = __vadd4(run, c);
            }
            tsum = __dp4a(run, 0x01010101u, 0u);   // total of 4 buckets
            inc = tsum;
#pragma unroll
            for (int d = 1; d < 32; d <<= 1) {
                unsigned int v = __shfl_up_sync(0xFFFFFFFFu, inc, d);
                if (lane >= d) inc += v;
            }
            if (lane == 31) wsum[wid] = inc;
        }
        __syncthreads();
        if (tid < 16) {                        // combine 12 warp totals
            unsigned int w = (tid < 12) ? wsum[tid] : 0u;
            unsigned int wi = w;
#pragma unroll
            for (int d = 1; d < 16; d <<= 1) {
                unsigned int v = __shfl_up_sync(0x0000FFFFu, wi, d);
                if (tid >= d) wi += v;
            }
            wsum[tid] = wi - w;                // exclusive warp offsets
        }
        __syncthreads();
        if (tid < 384) {
            unsigned int b0 = inc - tsum + wsum[wid];
            unsigned int b1 = b0 + (run & 0xFFu);
            unsigned int b2 = b1 + ((run >> 8) & 0xFFu);
            unsigned int b3 = b2 + ((run >> 16) & 0xFFu);
            *(uint4*)(base + 4 * tid) = make_uint4(b0, b1, b2, b3);
        }
        if (tid == 0) base[1536] = N_COLS;     // sentinel
    }
    __syncthreads();   // table reads done; keys[] may now be overwritten

    // ---- Phase 3: scatter keys to exact positions
    {
#pragma unroll
        for (int k = 0; k < 8; k++) {
            unsigned int b = bk[k] >> 8;
            unsigned int r = bk[k] & 0xFFu;
            unsigned int pos = base[b] + (unsigned int)whist[wid * NB + b] + r;
            keys[pos] = dk[k];
            bk[k] = (b << 13) | pos;          // repack (b<=1535:11b, pos:13b)
        }
    }
    __syncthreads();   // whist dead; sidx region may now be written

    // ---- Phase 4: exact rank, ONE compare per entry.
    // 4a: precompute packed bounds for all 8 k (16 independent base LDS,
    //     MLP-batched): bk[k] = start | len<<13 | off<<19  (len,off <= 63).
    {
#pragma unroll
        for (int k = 0; k < 8; k++) {
            unsigned int b = bk[k] >> 13;
            unsigned int pos = bk[k] & 0x1FFFu;
            unsigned int start = base[b];
            unsigned int end = base[b + 1];   // sentinel makes this safe
            bk[k] = start | ((end - start) << 13) | ((pos - start) << 19);
        }
    }
    // 4b: scan loops touch only registers + keys[]:
    // rank = #{key_j < mydk} + #{key_j == mydk && j < pos}:
    //   region [4*s4, 4*p4): count (key <= mydk)   (all j < pos)
    //   mid vector p4:       per-slot (lt | (eq & slot < pos%4))
    //   region (p4, e4):     count (key < mydk)    (all j > pos)
    // Left extras strictly smaller -> pre-subtracted; right extras strictly
    // larger -> +0. Exact for every tie configuration; no tie branch.
    {
        const uint4* k4 = (const uint4*)keys;
#pragma unroll
        for (int k = 0; k < 8; k++) {
            int start = (int)(bk[k] & 0x1FFFu);
            int end = start + (int)((bk[k] >> 13) & 63u);
            int pos = start + (int)((bk[k] >> 19) & 63u);
            unsigned int mydk = dk[k];
            int s4 = start >> 2;
            int p4 = pos >> 2;
            int e4 = (end + 3) >> 2;
            int rank = (s4 << 2) - start;     // subtract left extras
            for (int j = s4; j < p4; j++) {
                uint4 q = k4[j];
                rank += (int)(q.x <= mydk) + (int)(q.y <= mydk)
                      + (int)(q.z <= mydk) + (int)(q.w <= mydk);
            }
            {
                uint4 q = k4[p4];
                int pm = pos & 3;
                rank += (int)((q.x < mydk) | ((q.x == mydk) & (0 < pm)));
                rank += (int)((q.y < mydk) | ((q.y == mydk) & (1 < pm)));
                rank += (int)((q.z < mydk) | ((q.z == mydk) & (2 < pm)));
                rank += (int)((q.w < mydk) | ((q.w == mydk) & (3 < pm)));
            }
            for (int j = p4 + 1; j < e4; j++) {
                uint4 q = k4[j];
                rank += (int)(q.x < mydk) + (int)(q.y < mydk)
                      + (int)(q.z < mydk) + (int)(q.w < mydk);
            }
            sidx[start + rank] = (unsigned short)(wid * 256 + k * 32 + lane);
        }
    }
    __syncthreads();

    // ---- Phase 5: outputs
    if (write_indices) {
        float4* oidx4 = (float4*)(out + (size_t)B * N_COLS + (size_t)row * N_COLS);
        const uint2* s2 = (const uint2*)sidx;
#pragma unroll
        for (int g = 0; g < 2; g++) {
            uint2 a = s2[2 * tid + g];        // 4 u16 indices
            float4 f;
            f.x = (float)(a.x & 0xFFFFu);
            f.y = (float)(a.x >> 16);
            f.z = (float)(a.y & 0xFFFFu);
            f.w = (float)(a.y >> 16);
            oidx4[2 * tid + g] = f;
        }
    }

    // gather top/bot 20 (idx from sidx; value via tiny L2 gather)
    if (tid < 40) {
        int rnk = (tid < 20) ? tid : (N_COLS - 20 + (tid - 20));
        int idx = (int)sidx[rnk];
        sc_idx[tid] = idx;
        float x = rowp[idx];
        sc_val[tid] = (tid < 20) ? x : -x;
    }
    __syncthreads();  // orders the early zero-fill stores before the scatter

    if (tid < 40) {
        int g0 = (tid < 20) ? 0 : 20;
        float m = -1e30f;
#pragma unroll
        for (int j = 0; j < 20; j++) m = fmaxf(m, sc_val[g0 + j]);
        float s = 0.f;
#pragma unroll
        for (int j = 0; j < 20; j++) s += expf(sc_val[g0 + j] - m);
        float w = expf(sc_val[tid] - m) / s;
        ow[sc_idx[tid]] = (tid < 20) ? w : -w;
    }
}

extern "C" void kernel_launch(void* const* d_in, const int* in_sizes, int n_in,
                              void* d_out, int out_size) {
    const float* in = (const float*)d_in[0];
    float* out = (float*)d_out;
    int total = in_sizes[0];
    int B = total / N_COLS;
    int write_indices = (out_size >= 2 * total) ? 1 : 0;

    cudaFuncSetAttribute(pg_sort_kernel,
                         cudaFuncAttributeMaxDynamicSharedMemorySize, SMEM_BYTES);

    pg_build13<<<1, NT>>>();
    pg_sort_kernel<<<B, NT, SMEM_BYTES>>>(in, out, B, write_indices);
}

// round 16
// speedup vs baseline: 1.0808x; 1.0808x over previous
#include <cuda_runtime.h>
#include <stdint.h>

// Problem: B x N fp32 scores. Outputs (concatenated into float d_out):
//   [0, B*N)      portfolio_weights (sparse +softmax(top20), -softmax(bot20))
//   [B*N, 2*B*N)  sorted_indices of argsort(-scores) as float
#define N_COLS 8192
#define NB     1536   // bucket id space (used ids <= 1500)
#define NT     1024   // threads per CTA (one CTA per row)
#define NWARP  32
#define KBUCK  1500   // equal-probability bucket budget (avg ~5.5/bucket)

// 13-bit-prefix bucket table. For prefix p = dk >> 19:
//   entry = (base << 5) | cells   (base <= 1500 fits 11 bits, cells <= 31)
//   bucket = base + ((dk & 0x7FFFF) * cells) >> 19
__device__ unsigned short g_tab13[8192];

__device__ __forceinline__ float key_to_val(unsigned int dk) {
    unsigned int ukey = ~dk;
    return (ukey & 0x80000000u) ? __uint_as_float(ukey ^ 0x80000000u)
                                : __uint_as_float(~ukey);
}

__device__ __forceinline__ unsigned int desc_key(float x) {
    unsigned int u = __float_as_uint(x);
    unsigned int ukey = (u & 0x80000000u) ? ~u : (u | 0x80000000u);
    return ~ukey;   // ascending key == descending value
}

// Build table in ONE kernel (1 block x 1024 threads).
__global__ void pg_build13() {
    __shared__ unsigned int tmax[NT];
    __shared__ unsigned int fixed[8193];
    int t = threadIdx.x;
    unsigned int v[8];
    unsigned int cm = 0;
#pragma unroll
    for (int i = 0; i < 8; i++) {
        int p = t * 8 + i;
        float x = key_to_val(((unsigned int)p) << 19);
        float F;
        if (!(x == x)) F = (p < 4096) ? 0.f : 1.f;            // NaN prefixes
        else           F = normcdff(-fminf(fmaxf(x, -30.f), 30.f)); // 1-Phi(x)
        int b = (int)floorf(F * (float)KBUCK);
        b = b < 0 ? 0 : (b > KBUCK ? KBUCK : b);
        v[i] = (unsigned int)b;
        cm = max(cm, v[i]);
    }
    tmax[t] = cm;
    __syncthreads();
    for (int d = 1; d < NT; d <<= 1) {
        unsigned int w = (t >= d) ? tmax[t - d] : 0u;
        __syncthreads();
        if (t >= d) tmax[t] = max(tmax[t], w);
        __syncthreads();
    }
    unsigned int run = (t == 0) ? 0u : tmax[t - 1];
#pragma unroll
    for (int i = 0; i < 8; i++) {
        run = max(run, v[i]);
        fixed[t * 8 + i] = run;
    }
    if (t == 0) fixed[8192] = KBUCK;
    __syncthreads();
    for (int p = t; p < 8192; p += NT) {
        unsigned int b0 = fixed[p];
        unsigned int c = fixed[p + 1] - b0;
        if (c > 31u) c = 31u;
        g_tab13[p] = (unsigned short)((b0 << 5) | c);
    }
}

// ---------------------------------------------------------------------------
// Element ownership: warp wid owns elements [wid*256, wid*256+256);
// lane handles idx = wid*256 + k*32 + lane (k-major) so scatter position
// order within a bucket equals ascending original index (exact stable ties).
//
// SMEM layout (bytes):
//   [0,     32768)  keys u32[8192]   scattered keys, bucket-grouped (ph3+)
//   [32768, 49152)  sidx u16[8192]   rank->index (ph4+)
//                   ALIAS: tab13 u16[8192] bucket table (ph0-1 only)
//   [49152, 98304)  whist u8[32][1536] per-warp counts -> excl offs (ph1-3)
//   [98304,104452)  base u32[1537]   global excl bucket offsets + sentinel
//   [104464,104592) wsum u32[32]     scan staging
//   [104592,104752) sc_val f32[40]
//   [104752,104912) sc_idx i32[40]
// Total 104912 B -> two CTAs per SM (209824 <= 228KB) with regs <= 32.
// ---------------------------------------------------------------------------
#define SMEM_BYTES 104912

__global__ void __launch_bounds__(NT, 2)
pg_sort_kernel(const float* __restrict__ in, float* __restrict__ out,
               int B, int write_indices) {
    extern __shared__ unsigned char smem_raw[];
    unsigned int*   keys  = (unsigned int*)smem_raw;
    unsigned short* sidx  = (unsigned short*)(smem_raw + 32768);
    unsigned short* tab13 = (unsigned short*)(smem_raw + 32768);  // alias ph0-1
    unsigned char*  whist = (unsigned char*)(smem_raw + 49152);
    unsigned int*   base  = (unsigned int*)(smem_raw + 98304);
    unsigned int*   wsum  = (unsigned int*)(smem_raw + 104464);
    float* sc_val = (float*)(smem_raw + 104592);
    int*   sc_idx = (int*)  (smem_raw + 104752);

    int row = blockIdx.x;
    int tid = threadIdx.x;
    int lane = tid & 31;
    int wid = tid >> 5;
    const float* rowp = in + (size_t)row * N_COLS;
    float* ow = out + (size_t)row * N_COLS;

    // Phase 0: zero per-warp histograms (48KB) + copy table to smem (16KB)
    {
        uint4* wz = (uint4*)whist;
        uint4 z4 = make_uint4(0, 0, 0, 0);
        wz[tid] = z4;
        wz[tid + NT] = z4;
        wz[tid + 2 * NT] = z4;
        unsigned int* tsrc = (unsigned int*)g_tab13;
        unsigned int* tdst = (unsigned int*)tab13;
#pragma unroll
        for (int j = 0; j < 4; j++) tdst[tid + j * NT] = tsrc[tid + j * NT];
    }
    __syncthreads();

    // ---- Phase 1: branchless match-based per-warp ranking (k-major layout)
    unsigned int dk[8];
    unsigned int bk[8];                      // packed (bucket<<8)|warp_rank
    {
        int ebase = wid * 256 + lane;
        float vv[8];
#pragma unroll
        for (int k = 0; k < 8; k++) vv[k] = rowp[ebase + k * 32];  // MLP=8

        // Zero the output weights row NOW: the critical input LDGs above are
        // already issued, so these STGs drain to DRAM behind phases 1-4
        // instead of forming a tail. The later __syncthreads orders them
        // before the 40-weight scatter.
        {
            float4* ow4 = (float4*)ow;
            float4 z = make_float4(0.f, 0.f, 0.f, 0.f);
            ow4[tid] = z;
            ow4[tid + NT] = z;
        }

        unsigned char* wh = whist + wid * NB;
        unsigned int ltmask = (1u << lane) - 1u;
#pragma unroll
        for (int k = 0; k < 8; k++) {
            unsigned int d = desc_key(vv[k]);
            dk[k] = d;
            unsigned int e = (unsigned int)tab13[d >> 19];
            unsigned int b = (e >> 5) + (((d & 0x7FFFFu) * (e & 31u)) >> 19);
            unsigned int mask = __match_any_sync(0xFFFFFFFFu, b);
            unsigned int before = (unsigned int)wh[b];                 // all lanes
            wh[b] = (unsigned char)(before + (unsigned int)__popc(mask)); // same val
            bk[k] = (b << 8) | (before + (unsigned int)__popc(mask & ltmask));
            __syncwarp();
        }
    }
    __syncthreads();

    // ---- Phase 2: SIMD cross-warp exclusive offsets.
    // Thread t < 384 owns buckets [4t, 4t+4): u32 loads process 4 u8
    // counters at once; __vadd4 = per-byte add (no cross-byte carry).
    {
        unsigned int run = 0, tsum = 0, inc = 0;
        if (tid < 384) {
#pragma unroll
            for (int w = 0; w < NWARP; w++) {
                unsigned int* p32 = (unsigned int*)(whist + w * NB + 4 * tid);
                unsigned int c = *p32;
                *p32 = run;                    // packed per-warp exclusive
                run = __vadd4(run, c);
            }
            tsum = __dp4a(run, 0x01010101u, 0u);   // total of 4 buckets
            inc = tsum;
#pragma unroll
            for (int d = 1; d < 32; d <<= 1) {
                unsigned int v = __shfl_up_sync(0xFFFFFFFFu, inc, d);
                if (lane >= d) inc += v;
            }
            if (lane == 31) wsum[wid] = inc;
        }
        __syncthreads();
        if (tid < 16) {                        // combine 12 warp totals
            unsigned int w = (tid < 12) ? wsum[tid] : 0u;
            unsigned int wi = w;
#pragma unroll
            for (int d = 1; d < 16; d <<= 1) {
                unsigned int v = __shfl_up_sync(0x0000FFFFu, wi, d);
                if (tid >= d) wi += v;
            }
            wsum[tid] = wi - w;                // exclusive warp offsets
        }
        __syncthreads();
        if (tid < 384) {
            unsigned int b0 = inc - tsum + wsum[wid];
            unsigned int b1 = b0 + (run & 0xFFu);
            unsigned int b2 = b1 + ((run >> 8) & 0xFFu);
            unsigned int b3 = b2 + ((run >> 16) & 0xFFu);
            *(uint4*)(base + 4 * tid) = make_uint4(b0, b1, b2, b3);
        }
        if (tid == 0) base[1536] = N_COLS;     // sentinel
    }
    __syncthreads();   // table reads done; keys[] may now be overwritten

    // ---- Phase 3: scatter keys to exact positions
    {
#pragma unroll
        for (int k = 0; k < 8; k++) {
            unsigned int b = bk[k] >> 8;
            unsigned int r = bk[k] & 0xFFu;
            unsigned int pos = base[b] + (unsigned int)whist[wid * NB + b] + r;
            keys[pos] = dk[k];
            bk[k] = (b << 13) | pos;          // repack (b<=1535:11b, pos:13b)
        }
    }
    __syncthreads();   // whist dead; sidx region may now be written

    // ---- Phase 4: exact rank, ONE compare per entry.
    // rank = #{key_j < mydk} + #{key_j == mydk && j < pos}:
    //   region [4*s4, 4*p4): count (key <= mydk)   (all j < pos)
    //   mid vector p4:       per-slot (lt | (eq & slot < pos%4))
    //   region (p4, e4):     count (key < mydk)    (all j > pos)
    // Left extras strictly smaller -> pre-subtracted; right extras strictly
    // larger -> +0. Exact for every tie configuration; no tie branch.
    {
        const uint4* k4 = (const uint4*)keys;
#pragma unroll
        for (int k = 0; k < 8; k++) {
            unsigned int b = bk[k] >> 13;
            int pos = (int)(bk[k] & 0x1FFFu);
            int start = (int)base[b];
            int end = (int)base[b + 1];       // sentinel makes this safe
            unsigned int mydk = dk[k];
            int s4 = start >> 2;
            int p4 = pos >> 2;
            int e4 = (end + 3) >> 2;
            int rank = (s4 << 2) - start;     // subtract left extras
            for (int j = s4; j < p4; j++) {
                uint4 q = k4[j];
                rank += (int)(q.x <= mydk) + (int)(q.y <= mydk)
                      + (int)(q.z <= mydk) + (int)(q.w <= mydk);
            }
            {
                uint4 q = k4[p4];
                int pm = pos & 3;
                rank += (int)((q.x < mydk) | ((q.x == mydk) & (0 < pm)));
                rank += (int)((q.y < mydk) | ((q.y == mydk) & (1 < pm)));
                rank += (int)((q.z < mydk) | ((q.z == mydk) & (2 < pm)));
                rank += (int)((q.w < mydk) | ((q.w == mydk) & (3 < pm)));
            }
            for (int j = p4 + 1; j < e4; j++) {
                uint4 q = k4[j];
                rank += (int)(q.x < mydk) + (int)(q.y < mydk)
                      + (int)(q.z < mydk) + (int)(q.w < mydk);
            }
            sidx[start + rank] = (unsigned short)(wid * 256 + k * 32 + lane);
        }
    }
    __syncthreads();

    // ---- Phase 5: outputs
    if (write_indices) {
        float4* oidx4 = (float4*)(out + (size_t)B * N_COLS + (size_t)row * N_COLS);
        const uint2* s2 = (const uint2*)sidx;
#pragma unroll
        for (int g = 0; g < 2; g++) {
            uint2 a = s2[2 * tid + g];        // 4 u16 indices
            float4 f;
            f.x = (float)(a.x & 0xFFFFu);
            f.y = (float)(a.x >> 16);
            f.z = (float)(a.y & 0xFFFFu);
            f.w = (float)(a.y >> 16);
            oidx4[2 * tid + g] = f;
        }
    }

    // gather top/bot 20 (idx from sidx; value via tiny L2 gather)
    if (tid < 40) {
        int rnk = (tid < 20) ? tid : (N_COLS - 20 + (tid - 20));
        int idx = (int)sidx[rnk];
        sc_idx[tid] = idx;
        float x = rowp[idx];
        sc_val[tid] = (tid < 20) ? x : -x;
    }
    __syncthreads();  // orders the zero-fill stores before the scatter below

    if (tid < 40) {
        int g0 = (tid < 20) ? 0 : 20;
        float m = -1e30f;
#pragma unroll
        for (int j = 0; j < 20; j++) m = fmaxf(m, sc_val[g0 + j]);
        float s = 0.f;
#pragma unroll
        for (int j = 0; j < 20; j++) s += expf(sc_val[g0 + j] - m);
        float w = expf(sc_val[tid] - m) / s;
        ow[sc_idx[tid]] = (tid < 20) ? w : -w;
    }
}

extern "C" void kernel_launch(void* const* d_in, const int* in_sizes, int n_in,
                              void* d_out, int out_size) {
    const float* in = (const float*)d_in[0];
    float* out = (float*)d_out;
    int total = in_sizes[0];
    int B = total / N_COLS;
    int write_indices = (out_size >= 2 * total) ? 1 : 0;

    cudaFuncSetAttribute(pg_sort_kernel,
                         cudaFuncAttributeMaxDynamicSharedMemorySize, SMEM_BYTES);

    pg_build13<<<1, NT>>>();
    pg_sort_kernel<<<B, NT, SMEM_BYTES>>>(in, out, B, write_indices);
}

// round 17
// speedup vs baseline: 1.0944x; 1.0126x over previous
#include <cuda_runtime.h>
#include <stdint.h>

// Problem: B x N fp32 scores. Outputs (concatenated into float d_out):
//   [0, B*N)      portfolio_weights (sparse +softmax(top20), -softmax(bot20))
//   [B*N, 2*B*N)  sorted_indices of argsort(-scores) as float
#define N_COLS 8192
#define NB     1536   // bucket id space (used ids <= 1500)
#define NT     1024   // threads per CTA (one CTA per row)
#define NWARP  32
#define KBUCK  1500   // equal-probability bucket budget (avg ~5.5/bucket)

// 13-bit-prefix bucket table. For prefix p = dk >> 19:
//   entry = (base << 5) | cells   (base <= 1500 fits 11 bits, cells <= 31)
//   bucket = base + ((dk & 0x7FFFF) * cells) >> 19
__device__ unsigned short g_tab13[8192];

__device__ __forceinline__ float key_to_val(unsigned int dk) {
    unsigned int ukey = ~dk;
    return (ukey & 0x80000000u) ? __uint_as_float(ukey ^ 0x80000000u)
                                : __uint_as_float(~ukey);
}

__device__ __forceinline__ unsigned int desc_key(float x) {
    unsigned int u = __float_as_uint(x);
    unsigned int ukey = (u & 0x80000000u) ? ~u : (u | 0x80000000u);
    return ~ukey;   // ascending key == descending value
}

// Build table in ONE kernel (1 block x 1024 threads).
__global__ void pg_build13() {
    __shared__ unsigned int tmax[NT];
    __shared__ unsigned int fixed[8193];
    int t = threadIdx.x;
    unsigned int v[8];
    unsigned int cm = 0;
#pragma unroll
    for (int i = 0; i < 8; i++) {
        int p = t * 8 + i;
        float x = key_to_val(((unsigned int)p) << 19);
        float F;
        if (!(x == x)) F = (p < 4096) ? 0.f : 1.f;            // NaN prefixes
        else           F = normcdff(-fminf(fmaxf(x, -30.f), 30.f)); // 1-Phi(x)
        int b = (int)floorf(F * (float)KBUCK);
        b = b < 0 ? 0 : (b > KBUCK ? KBUCK : b);
        v[i] = (unsigned int)b;
        cm = max(cm, v[i]);
    }
    tmax[t] = cm;
    __syncthreads();
    for (int d = 1; d < NT; d <<= 1) {
        unsigned int w = (t >= d) ? tmax[t - d] : 0u;
        __syncthreads();
        if (t >= d) tmax[t] = max(tmax[t], w);
        __syncthreads();
    }
    unsigned int run = (t == 0) ? 0u : tmax[t - 1];
#pragma unroll
    for (int i = 0; i < 8; i++) {
        run = max(run, v[i]);
        fixed[t * 8 + i] = run;
    }
    if (t == 0) fixed[8192] = KBUCK;
    __syncthreads();
    for (int p = t; p < 8192; p += NT) {
        unsigned int b0 = fixed[p];
        unsigned int c = fixed[p + 1] - b0;
        if (c > 31u) c = 31u;
        g_tab13[p] = (unsigned short)((b0 << 5) | c);
    }
}

// ---------------------------------------------------------------------------
// Element ownership: warp wid owns elements [wid*256, wid*256+256);
// lane handles idx = wid*256 + k*32 + lane (k-major) so scatter position
// order within a bucket equals ascending original index (exact stable ties).
//
// SMEM layout (bytes):
//   [0,     32768)  keys u32[8192]   scattered keys, bucket-grouped (ph3+)
//   [32768, 49152)  sidx u16[8192]   rank->index (ph4+)
//                   ALIAS: tab13 u16[8192] bucket table (ph0-1 only)
//   [49152, 98304)  whist u8[32][1536] per-warp counts -> excl offs (ph1-3)
//   [98304,104452)  base u32[1537]   global excl bucket offsets + sentinel
//   [104464,104592) wsum u32[32]     scan staging
//   [104592,104752) sc_val f32[40]
//   [104752,104912) sc_idx i32[40]
// Total 104912 B -> two CTAs per SM (209824 <= 228KB) with regs <= 32.
// ---------------------------------------------------------------------------
#define SMEM_BYTES 104912

__global__ void __launch_bounds__(NT, 2)
pg_sort_kernel(const float* __restrict__ in, float* __restrict__ out,
               int B, int write_indices) {
    extern __shared__ unsigned char smem_raw[];
    unsigned int*   keys  = (unsigned int*)smem_raw;
    unsigned short* sidx  = (unsigned short*)(smem_raw + 32768);
    unsigned short* tab13 = (unsigned short*)(smem_raw + 32768);  // alias ph0-1
    unsigned char*  whist = (unsigned char*)(smem_raw + 49152);
    unsigned int*   base  = (unsigned int*)(smem_raw + 98304);
    unsigned int*   wsum  = (unsigned int*)(smem_raw + 104464);
    float* sc_val = (float*)(smem_raw + 104592);
    int*   sc_idx = (int*)  (smem_raw + 104752);

    int row = blockIdx.x;
    int tid = threadIdx.x;
    int lane = tid & 31;
    int wid = tid >> 5;
    const float* rowp = in + (size_t)row * N_COLS;
    float* ow = out + (size_t)row * N_COLS;

    // Phase 0: zero per-warp histograms (48KB) + copy table to smem (16KB)
    {
        uint4* wz = (uint4*)whist;
        uint4 z4 = make_uint4(0, 0, 0, 0);
        wz[tid] = z4;
        wz[tid + NT] = z4;
        wz[tid + 2 * NT] = z4;
        unsigned int* tsrc = (unsigned int*)g_tab13;
        unsigned int* tdst = (unsigned int*)tab13;
#pragma unroll
        for (int j = 0; j < 4; j++) tdst[tid + j * NT] = tsrc[tid + j * NT];
    }
    __syncthreads();

    // ---- Phase 1: branchless match-based per-warp ranking (k-major layout)
    unsigned int dk[8];
    unsigned int bk[8];                      // packed (bucket<<8)|warp_rank
    {
        int ebase = wid * 256 + lane;
        float vv[8];
#pragma unroll
        for (int k = 0; k < 8; k++) vv[k] = rowp[ebase + k * 32];  // MLP=8

        // Zero the output weights row NOW: the critical input LDGs above are
        // already issued, so these STGs drain to DRAM behind phases 1-4
        // instead of forming a tail. The later __syncthreads orders them
        // before the 40-weight scatter.
        {
            float4* ow4 = (float4*)ow;
            float4 z = make_float4(0.f, 0.f, 0.f, 0.f);
            ow4[tid] = z;
            ow4[tid + NT] = z;
        }

        unsigned char* wh = whist + wid * NB;
        unsigned int ltmask = (1u << lane) - 1u;
#pragma unroll
        for (int k = 0; k < 8; k++) {
            unsigned int d = desc_key(vv[k]);
            dk[k] = d;
            unsigned int e = (unsigned int)tab13[d >> 19];
            unsigned int b = (e >> 5) + (((d & 0x7FFFFu) * (e & 31u)) >> 19);
            unsigned int mask = __match_any_sync(0xFFFFFFFFu, b);
            unsigned int before = (unsigned int)wh[b];                 // all lanes
            wh[b] = (unsigned char)(before + (unsigned int)__popc(mask)); // same val
            bk[k] = (b << 8) | (before + (unsigned int)__popc(mask & ltmask));
            __syncwarp();
        }
    }
    __syncthreads();

    // ---- Phase 2: SIMD cross-warp exclusive offsets.
    // Thread t < 384 owns buckets [4t, 4t+4): u32 loads process 4 u8
    // counters at once; __vadd4 = per-byte add (no cross-byte carry).
    {
        unsigned int run = 0, tsum = 0, inc = 0;
        if (tid < 384) {
#pragma unroll
            for (int w = 0; w < NWARP; w++) {
                unsigned int* p32 = (unsigned int*)(whist + w * NB + 4 * tid);
                unsigned int c = *p32;
                *p32 = run;                    // packed per-warp exclusive
                run = __vadd4(run, c);
            }
            tsum = __dp4a(run, 0x01010101u, 0u);   // total of 4 buckets
            inc = tsum;
#pragma unroll
            for (int d = 1; d < 32; d <<= 1) {
                unsigned int v = __shfl_up_sync(0xFFFFFFFFu, inc, d);
                if (lane >= d) inc += v;
            }
            if (lane == 31) wsum[wid] = inc;
        }
        __syncthreads();
        if (tid < 16) {                        // combine 12 warp totals
            unsigned int w = (tid < 12) ? wsum[tid] : 0u;
            unsigned int wi = w;
#pragma unroll
            for (int d = 1; d < 16; d <<= 1) {
                unsigned int v = __shfl_up_sync(0x0000FFFFu, wi, d);
                if (tid >= d) wi += v;
            }
            wsum[tid] = wi - w;                // exclusive warp offsets
        }
        __syncthreads();
        if (tid < 384) {
            unsigned int b0 = inc - tsum + wsum[wid];
            unsigned int b1 = b0 + (run & 0xFFu);
            unsigned int b2 = b1 + ((run >> 8) & 0xFFu);
            unsigned int b3 = b2 + ((run >> 16) & 0xFFu);
            *(uint4*)(base + 4 * tid) = make_uint4(b0, b1, b2, b3);
        }
        if (tid == 0) base[1536] = N_COLS;     // sentinel
    }
    __syncthreads();   // table reads done; keys[] may now be overwritten

    // ---- Phase 3: scatter keys to exact positions
    {
#pragma unroll
        for (int k = 0; k < 8; k++) {
            unsigned int b = bk[k] >> 8;
            unsigned int r = bk[k] & 0xFFu;
            unsigned int pos = base[b] + (unsigned int)whist[wid * NB + b] + r;
            keys[pos] = dk[k];
            bk[k] = (b << 13) | pos;          // repack (b<=1535:11b, pos:13b)
        }
    }
    __syncthreads();   // whist dead; sidx region may now be written

    // ---- Phase 4: exact rank, SINGLE dynamic loop per element.
    // Per slot at position p: counts iff (key < mydk) OR (key == mydk AND
    // p < pos). Position order == original-index order, so the position
    // compare IS the exact stable tie-break; self excluded (pos < pos).
    // Left alignment extras are strictly smaller (counted by the lt term,
    // pre-subtracted); right extras strictly larger (count 0).
    {
        const uint4* k4 = (const uint4*)keys;
#pragma unroll
        for (int k = 0; k < 8; k++) {
            unsigned int b = bk[k] >> 13;
            int pos = (int)(bk[k] & 0x1FFFu);
            int start = (int)base[b];
            int end = (int)base[b + 1];       // sentinel makes this safe
            unsigned int mydk = dk[k];
            int s4 = start >> 2;
            int e4 = (end + 3) >> 2;
            int rank = (s4 << 2) - start;     // subtract left extras
            for (int j = s4; j < e4; j++) {
                uint4 q = k4[j];
                int j4 = j << 2;
                rank += (int)((q.x < mydk) | ((q.x == mydk) & (j4 + 0 < pos)));
                rank += (int)((q.y < mydk) | ((q.y == mydk) & (j4 + 1 < pos)));
                rank += (int)((q.z < mydk) | ((q.z == mydk) & (j4 + 2 < pos)));
                rank += (int)((q.w < mydk) | ((q.w == mydk) & (j4 + 3 < pos)));
            }
            sidx[start + rank] = (unsigned short)(wid * 256 + k * 32 + lane);
        }
    }
    __syncthreads();

    // ---- Phase 5: outputs
    if (write_indices) {
        float4* oidx4 = (float4*)(out + (size_t)B * N_COLS + (size_t)row * N_COLS);
        const uint2* s2 = (const uint2*)sidx;
#pragma unroll
        for (int g = 0; g < 2; g++) {
            uint2 a = s2[2 * tid + g];        // 4 u16 indices
            float4 f;
            f.x = (float)(a.x & 0xFFFFu);
            f.y = (float)(a.x >> 16);
            f.z = (float)(a.y & 0xFFFFu);
            f.w = (float)(a.y >> 16);
            oidx4[2 * tid + g] = f;
        }
    }

    // gather top/bot 20 (idx from sidx; value via tiny L2 gather)
    if (tid < 40) {
        int rnk = (tid < 20) ? tid : (N_COLS - 20 + (tid - 20));
        int idx = (int)sidx[rnk];
        sc_idx[tid] = idx;
        float x = rowp[idx];
        sc_val[tid] = (tid < 20) ? x : -x;
    }
    __syncthreads();  // orders the zero-fill stores before the scatter below

    if (tid < 40) {
        int g0 = (tid < 20) ? 0 : 20;
        float m = -1e30f;
#pragma unroll
        for (int j = 0; j < 20; j++) m = fmaxf(m, sc_val[g0 + j]);
        float s = 0.f;
#pragma unroll
        for (int j = 0; j < 20; j++) s += expf(sc_val[g0 + j] - m);
        float w = expf(sc_val[tid] - m) / s;
        ow[sc_idx[tid]] = (tid < 20) ? w : -w;
    }
}

extern "C" void kernel_launch(void* const* d_in, const int* in_sizes, int n_in,
                              void* d_out, int out_size) {
    const float* in = (const float*)d_in[0];
    float* out = (float*)d_out;
    int total = in_sizes[0];
    int B = total / N_COLS;
    int write_indices = (out_size >= 2 * total) ? 1 : 0;

    cudaFuncSetAttribute(pg_sort_kernel,
                         cudaFuncAttributeMaxDynamicSharedMemorySize, SMEM_BYTES);

    pg_build13<<<1, NT>>>();
    pg_sort_kernel<<<B, NT, SMEM_BYTES>>>(in, out, B, write_indices);
}